// round 6
// baseline (speedup 1.0000x reference)
#include <cuda_runtime.h>
#include <cstdint>

typedef unsigned long long ull;

// ---------------------------------------------------------------------------
//   img      [64][3][416][416]
//   conv1    5x5 VALID -> relu -> pool2 -> [64][6][206][206]
//   conv2    5x5 VALID -> relu -> pool2 -> [64][16][101][101]
//   fc1      [64][163216] -> relu -> [64][64] -> boxes [1024][4]
//   roipool  -> [1024][3][16][16] -> 4x4 conv -> relu -> fc2 -> [1024][64]
// ---------------------------------------------------------------------------

__device__ float g_pool1[64 * 6 * 206 * 206];
__device__ float g_pool2[64 * 16 * 101 * 101];
__device__ float g_fc1part[101 * 64 * 64];
__device__ float4 g_roi[1024];

// ---- packed fp32x2 helpers ------------------------------------------------
__device__ __forceinline__ ull fma2(ull a, ull b, ull c) {
    ull d;
    asm("fma.rn.f32x2 %0, %1, %2, %3;" : "=l"(d) : "l"(a), "l"(b), "l"(c));
    return d;
}
__device__ __forceinline__ ull dup2(float v) {
    ull d;
    asm("mov.b64 %0, {%1, %1};" : "=l"(d) : "f"(v));
    return d;
}
__device__ __forceinline__ float2 unpk(ull a) {
    float2 r;
    asm("mov.b64 {%0, %1}, %2;" : "=f"(r.x), "=f"(r.y) : "l"(a));
    return r;
}

// ---------------------------------------------------------------------------
// conv1 + relu + maxpool2.  (R2 version — measured fastest)
// ---------------------------------------------------------------------------
__global__ __launch_bounds__(256) void conv1_kernel(
    const float* __restrict__ img, const float* __restrict__ w,
    const float* __restrict__ bias) {
    __shared__ float sin[3][36 * 69];
    __shared__ float2 swp[3 * 25 * 3];   // [(ic*25+k)*3 + p]
    __shared__ float sb[6];
    const int bz = blockIdx.z, by = blockIdx.y, bx = blockIdx.x;
    const int tid = threadIdx.x;

    if (tid < 225) {
        int p = tid % 3, ick = tid / 3;
        int ic = ick / 25, k = ick % 25;
        swp[tid] = make_float2(w[(2 * p) * 75 + ic * 25 + k],
                               w[(2 * p + 1) * 75 + ic * 25 + k]);
    }
    if (tid < 6) sb[tid] = bias[tid];

    const int iy0 = by * 32, ix0 = bx * 64;
    for (int e = tid; e < 3 * 36 * 68; e += 256) {
        int ic = e / 2448, rem = e % 2448, r = rem / 68, c = rem % 68;
        int gy = iy0 + r, gx = ix0 + c;
        float v = 0.f;
        if (gy < 416 && gx < 416)
            v = img[((size_t)bz * 3 + ic) * 416 * 416 + gy * 416 + gx];
        sin[ic][r * 69 + c] = v;
    }
    __syncthreads();

    const int ty = tid >> 4, tx = tid & 15;
    ull acc[3][2][4];
#pragma unroll
    for (int p = 0; p < 3; p++)
#pragma unroll
        for (int r = 0; r < 2; r++)
#pragma unroll
            for (int c = 0; c < 4; c++) acc[p][r][c] = 0ull;

    for (int ic = 0; ic < 3; ic++) {
        const float* S = &sin[ic][(2 * ty) * 69 + 4 * tx];
        const ull* W = (const ull*)&swp[ic * 75];
        ull RA[8], RB[8];
#pragma unroll
        for (int c = 0; c < 8; c++) RA[c] = dup2(S[c]);
#pragma unroll
        for (int ky = 0; ky < 5; ky++) {
            const float* Srow = S + (ky + 1) * 69;
#pragma unroll
            for (int c = 0; c < 8; c++) RB[c] = dup2(Srow[c]);
#pragma unroll
            for (int kx = 0; kx < 5; kx++) {
#pragma unroll
                for (int p = 0; p < 3; p++) {
                    ull wv = W[(ky * 5 + kx) * 3 + p];
#pragma unroll
                    for (int c = 0; c < 4; c++) {
                        acc[p][0][c] = fma2(RA[kx + c], wv, acc[p][0][c]);
                        acc[p][1][c] = fma2(RB[kx + c], wv, acc[p][1][c]);
                    }
                }
            }
#pragma unroll
            for (int c = 0; c < 8; c++) RA[c] = RB[c];
        }
    }

    const int py = by * 16 + ty;
    if (py < 206) {
#pragma unroll
        for (int d = 0; d < 2; d++) {
            const int px = bx * 32 + 2 * tx + d;
            if (px < 206) {
#pragma unroll
                for (int p = 0; p < 3; p++) {
                    float2 a00 = unpk(acc[p][0][2 * d]);
                    float2 a01 = unpk(acc[p][0][2 * d + 1]);
                    float2 a10 = unpk(acc[p][1][2 * d]);
                    float2 a11 = unpk(acc[p][1][2 * d + 1]);
                    float vlo = fmaxf(fmaxf(a00.x, a01.x), fmaxf(a10.x, a11.x));
                    float vhi = fmaxf(fmaxf(a00.y, a01.y), fmaxf(a10.y, a11.y));
                    g_pool1[(((size_t)bz * 6 + 2 * p) * 206 + py) * 206 + px] =
                        fmaxf(vlo + sb[2 * p], 0.f);
                    g_pool1[(((size_t)bz * 6 + 2 * p + 1) * 206 + py) * 206 + px] =
                        fmaxf(vhi + sb[2 * p + 1], 0.f);
                }
            }
        }
    }
}

// ---------------------------------------------------------------------------
// conv2 + relu + maxpool2.  (R2 version — measured fastest)
// ---------------------------------------------------------------------------
__global__ __launch_bounds__(256) void conv2_kernel(
    const float* __restrict__ w, const float* __restrict__ bias) {
    __shared__ float sin[6][36 * 37];
    __shared__ float2 swp[6 * 25 * 8];   // [(ic*25+k)*8 + p]
    __shared__ float sb[16];
    const int bz = blockIdx.z, by = blockIdx.y, bx = blockIdx.x;
    const int tid = threadIdx.x;

    for (int i = tid; i < 1200; i += 256) {
        int p = i % 8, ick = i / 8;
        int ic = ick / 25, k = ick % 25;
        swp[i] = make_float2(w[((2 * p) * 6 + ic) * 25 + k],
                             w[((2 * p + 1) * 6 + ic) * 25 + k]);
    }
    if (tid < 16) sb[tid] = bias[tid];

    const int iy0 = by * 32, ix0 = bx * 32;
    for (int e = tid; e < 6 * 36 * 36; e += 256) {
        int ic = e / 1296, rem = e % 1296, r = rem / 36, c = rem % 36;
        int gy = iy0 + r, gx = ix0 + c;
        float v = 0.f;
        if (gy < 206 && gx < 206)
            v = g_pool1[(((size_t)bz * 6 + ic) * 206 + gy) * 206 + gx];
        sin[ic][r * 37 + c] = v;
    }
    __syncthreads();

    const int og = tid >> 7;            // 0..1 -> oc base 8*og
    const int t = tid & 127;
    const int ty = t >> 3, tx = t & 7;
    ull acc[4][2][4];
#pragma unroll
    for (int p = 0; p < 4; p++)
#pragma unroll
        for (int r = 0; r < 2; r++)
#pragma unroll
            for (int c = 0; c < 4; c++) acc[p][r][c] = 0ull;

    for (int ic = 0; ic < 6; ic++) {
        const float* S = &sin[ic][(2 * ty) * 37 + 4 * tx];
        const ull* W = (const ull*)&swp[ic * 200 + 4 * og];
        ull RA[8], RB[8];
#pragma unroll
        for (int c = 0; c < 8; c++) RA[c] = dup2(S[c]);
#pragma unroll
        for (int ky = 0; ky < 5; ky++) {
            const float* Srow = S + (ky + 1) * 37;
#pragma unroll
            for (int c = 0; c < 8; c++) RB[c] = dup2(Srow[c]);
#pragma unroll
            for (int kx = 0; kx < 5; kx++) {
#pragma unroll
                for (int p = 0; p < 4; p++) {
                    ull wv = W[(ky * 5 + kx) * 8 + p];
#pragma unroll
                    for (int c = 0; c < 4; c++) {
                        acc[p][0][c] = fma2(RA[kx + c], wv, acc[p][0][c]);
                        acc[p][1][c] = fma2(RB[kx + c], wv, acc[p][1][c]);
                    }
                }
            }
#pragma unroll
            for (int c = 0; c < 8; c++) RA[c] = RB[c];
        }
    }

    const int py = by * 16 + ty;
    if (py < 101) {
#pragma unroll
        for (int d = 0; d < 2; d++) {
            const int px = bx * 16 + 2 * tx + d;
            if (px < 101) {
#pragma unroll
                for (int p = 0; p < 4; p++) {
                    const int oc = 8 * og + 2 * p;
                    float2 a00 = unpk(acc[p][0][2 * d]);
                    float2 a01 = unpk(acc[p][0][2 * d + 1]);
                    float2 a10 = unpk(acc[p][1][2 * d]);
                    float2 a11 = unpk(acc[p][1][2 * d + 1]);
                    float vlo = fmaxf(fmaxf(a00.x, a01.x), fmaxf(a10.x, a11.x));
                    float vhi = fmaxf(fmaxf(a00.y, a01.y), fmaxf(a10.y, a11.y));
                    g_pool2[(((size_t)bz * 16 + oc) * 101 + py) * 101 + px] =
                        fmaxf(vlo + sb[oc], 0.f);
                    g_pool2[(((size_t)bz * 16 + oc + 1) * 101 + py) * 101 + px] =
                        fmaxf(vhi + sb[oc + 1], 0.f);
                }
            }
        }
    }
}

// ---------------------------------------------------------------------------
// fc1 split-K with f32x2 over output-col pairs. Transposed smem [kk][col].
// ---------------------------------------------------------------------------
__global__ __launch_bounds__(256) void fc1_kernel(const float* __restrict__ w) {
    __shared__ float xs[16][66];   // [kk][batch]
    __shared__ float ws[16][66];   // [kk][outcol]
    const int blk = blockIdx.x;
    const int tid = threadIdx.x;
    const int tb = tid >> 4, to = tid & 15;
    ull acc[4][2];
#pragma unroll
    for (int i = 0; i < 4; i++) acc[i][0] = acc[i][1] = 0ull;

    const int k0 = blk * 1616;
    for (int s = 0; s < 101; s++) {
        const int kbase = k0 + s * 16;
#pragma unroll
        for (int i = 0; i < 4; i++) {
            int e = tid + i * 256;
            int row = e >> 4, col = e & 15;   // row: batch/outcol, col: kk
            xs[col][row] = g_pool2[(size_t)row * 163216 + kbase + col];
            ws[col][row] = w[(size_t)row * 163216 + kbase + col];
        }
        __syncthreads();
#pragma unroll
        for (int kk = 0; kk < 16; kk++) {
            ull wr0 = *(const ull*)&ws[kk][2 * to];
            ull wr1 = *(const ull*)&ws[kk][2 * to + 32];
#pragma unroll
            for (int i = 0; i < 4; i++) {
                ull xv = dup2(xs[kk][tb + 16 * i]);
                acc[i][0] = fma2(xv, wr0, acc[i][0]);
                acc[i][1] = fma2(xv, wr1, acc[i][1]);
            }
        }
        __syncthreads();
    }

    float* outp = g_fc1part + (size_t)blk * 4096;
#pragma unroll
    for (int i = 0; i < 4; i++) {
        float2 a0 = unpk(acc[i][0]);
        float2 a1 = unpk(acc[i][1]);
        const int row = tb + 16 * i;
        outp[row * 64 + 2 * to] = a0.x;
        outp[row * 64 + 2 * to + 1] = a0.y;
        outp[row * 64 + 2 * to + 32] = a1.x;
        outp[row * 64 + 2 * to + 33] = a1.y;
    }
}

// ---------------------------------------------------------------------------
// fc1 finalize + box decode. 64 blocks, coalesced reduction over partials.
// ---------------------------------------------------------------------------
__global__ __launch_bounds__(256) void fc1_finalize_boxes(
    const float* __restrict__ fc1_b) {
    __shared__ float partial[4][64];
    __shared__ float xv[64];
    const int b = blockIdx.x;
    const int tid = threadIdx.x;
    const int j = tid & 63, ch = tid >> 6;
    float s = 0.f;
    for (int t = ch; t < 101; t += 4)
        s += g_fc1part[t * 4096 + b * 64 + j];
    partial[ch][j] = s;
    __syncthreads();
    if (tid < 64) {
        float v = partial[0][tid] + partial[1][tid] + partial[2][tid] +
                  partial[3][tid] + fc1_b[tid];
        xv[tid] = fmaxf(v, 0.f);
    }
    __syncthreads();
    if (tid < 16) {
        const int i = tid;
        float x1 = fminf(fmaxf(rintf(xv[i] * 0.5f), 0.f), 415.f);
        float y1 = fminf(fmaxf(rintf(xv[16 + i] * 0.5f), 0.f), 415.f);
        float x2 = fminf(fmaxf(rintf(xv[32 + i] * 0.5f), 0.f), 415.f);
        float y2 = fminf(fmaxf(rintf(xv[48 + i] * 0.5f), 0.f), 415.f);
        float bw = fmaxf(x2 - x1 + 1.f, 1.f) * (1.f / 16.f);
        float bh = fmaxf(y2 - y1 + 1.f, 1.f) * (1.f / 16.f);
        g_roi[b * 16 + i] = make_float4(x1, y1, bw, bh);
    }
}

// ---------------------------------------------------------------------------
// Fused RoIPool + 4x4 conv + fc2. One block per roi.
// Separable, fully-coalesced variant: per channel,
//   phase 1: rowmax[ph][x] over the bin's y-extent, threads contiguous in x;
//   phase 2: 256 threads (= 16x16 bins) reduce rowmax over the x-extent.
// Same pixel-read count as the naive scan, ~4x fewer L2 sectors.
// ---------------------------------------------------------------------------
__global__ __launch_bounds__(256) void roi_kernel(
    const float* __restrict__ img, const float* __restrict__ rw,
    const float* __restrict__ rb, const float* __restrict__ w2,
    const float* __restrict__ b2, float* __restrict__ out) {
    __shared__ float rowmax[16][420];
    __shared__ float pooled[3][16][16];
    __shared__ float yv[169];
    __shared__ float swc[48];
    __shared__ float sbc;
    __shared__ int hs_s[16], he_s[16], ws_s[16], we_s[16];
    const int n = blockIdx.x, tid = threadIdx.x;

    if (tid < 48) swc[tid] = rw[tid];
    if (tid == 0) sbc = rb[0];

    const float4 p = g_roi[n];   // x1, y1, bw, bh
    const int b = n >> 4;
    const float* imgb = img + (size_t)b * 3 * 416 * 416;

    if (tid < 16) {
        hs_s[tid] = (int)fminf(floorf((float)tid * p.w) + p.y, 416.f);
        he_s[tid] = (int)fminf(ceilf((float)(tid + 1) * p.w) + p.y, 416.f);
    } else if (tid < 32) {
        const int pw = tid - 16;
        ws_s[pw] = (int)fminf(floorf((float)pw * p.z) + p.x, 416.f);
        we_s[pw] = (int)fminf(ceilf((float)(pw + 1) * p.z) + p.x, 416.f);
    }
    const int x1i = (int)p.x;
    const int xend = (int)fminf(ceilf(16.f * p.z) + p.x, 416.f);
    const int width = xend - x1i;
    __syncthreads();

    const int ph2 = tid >> 4, pw2 = tid & 15;
    const int wsb = ws_s[pw2], web = we_s[pw2];
    const int hsb = hs_s[ph2], heb = he_s[ph2];

#pragma unroll 1
    for (int chn = 0; chn < 3; chn++) {
        const float* cbase = imgb + (size_t)chn * 416 * 416;
        // phase 1: coalesced row-band maxes
        for (int e = tid; e < 16 * width; e += 256) {
            const int ph = e / width, xo = e - ph * width;
            const int x = x1i + xo;
            const int hs = hs_s[ph], he = he_s[ph];
            float m = -3.4e38f;
            const float* col = cbase + hs * 416 + x;
#pragma unroll 2
            for (int yy = hs; yy < he; yy++) {
                m = fmaxf(m, *col);
                col += 416;
            }
            rowmax[ph][xo] = m;
        }
        __syncthreads();
        // phase 2: per-bin x reduction from smem
        {
            float m = -3.4e38f;
#pragma unroll 2
            for (int xx = wsb - x1i; xx < web - x1i; xx++)
                m = fmaxf(m, rowmax[ph2][xx]);
            pooled[chn][ph2][pw2] = (heb > hsb && web > wsb) ? m : 0.f;
        }
        __syncthreads();
    }

    if (tid < 169) {
        const int oy = tid / 13, ox = tid % 13;
        float s = sbc;
#pragma unroll
        for (int c = 0; c < 3; c++)
#pragma unroll
            for (int ky = 0; ky < 4; ky++)
#pragma unroll
                for (int kx = 0; kx < 4; kx++)
                    s = fmaf(pooled[c][oy + ky][ox + kx],
                             swc[(c * 4 + ky) * 4 + kx], s);
        yv[tid] = fmaxf(s, 0.f);
    }
    __syncthreads();

    if (tid < 64) {
        float s = b2[tid];
        const float* wr = w2 + tid * 169;
        for (int pp = 0; pp < 169; pp++) s = fmaf(yv[pp], __ldg(&wr[pp]), s);
        out[(size_t)n * 64 + tid] = fmaxf(s, 0.f);
    }
}

// ---------------------------------------------------------------------------
extern "C" void kernel_launch(void* const* d_in, const int* in_sizes, int n_in,
                              void* d_out, int out_size) {
    const float* img     = (const float*)d_in[0];
    const float* conv1_w = (const float*)d_in[1];
    const float* conv1_b = (const float*)d_in[2];
    const float* conv2_w = (const float*)d_in[3];
    const float* conv2_b = (const float*)d_in[4];
    const float* fc1_w   = (const float*)d_in[5];
    const float* fc1_b   = (const float*)d_in[6];
    const float* roi_w   = (const float*)d_in[7];
    const float* roi_b   = (const float*)d_in[8];
    const float* fc2_w   = (const float*)d_in[9];
    const float* fc2_b   = (const float*)d_in[10];
    float* out = (float*)d_out;

    dim3 g1(7, 13, 64);    // pooled 206: x 7*32=224, y 13*16=208
    conv1_kernel<<<g1, 256>>>(img, conv1_w, conv1_b);

    dim3 g2(7, 7, 64);     // pooled 101: 7*16=112 both dims
    conv2_kernel<<<g2, 256>>>(conv2_w, conv2_b);

    fc1_kernel<<<101, 256>>>(fc1_w);
    fc1_finalize_boxes<<<64, 256>>>(fc1_b);
    roi_kernel<<<1024, 256>>>(img, roi_w, roi_b, fc2_w, fc2_b, out);
}

// round 7
// speedup vs baseline: 1.1102x; 1.1102x over previous
#include <cuda_runtime.h>
#include <cstdint>

typedef unsigned long long ull;

// ---------------------------------------------------------------------------
//   img      [64][3][416][416]
//   conv1    5x5 VALID -> relu -> pool2 -> [64][6][206][206] (stored 208x208 padded)
//   conv2    5x5 VALID -> relu -> pool2 -> [64][16][101][101]
//   fc1      [64][163216] -> relu -> [64][64] -> boxes [1024][4]
//   roipool  -> [1024][3][16][16] -> 4x4 conv -> relu -> fc2 -> [1024][64]
// ---------------------------------------------------------------------------

// padded 208x208 (rows/cols 206..207 are never written; static zero-init
// provides the zero padding conv2's masking expects)
__device__ float g_pool1[64 * 6 * 208 * 208];
__device__ float g_pool2[64 * 16 * 101 * 101];
__device__ float g_fc1part[101 * 64 * 64];
__device__ float4 g_roi[1024];

// ---- packed fp32x2 helpers ------------------------------------------------
__device__ __forceinline__ ull fma2(ull a, ull b, ull c) {
    ull d;
    asm("fma.rn.f32x2 %0, %1, %2, %3;" : "=l"(d) : "l"(a), "l"(b), "l"(c));
    return d;
}
__device__ __forceinline__ ull dup2(float v) {
    ull d;
    asm("mov.b64 %0, {%1, %1};" : "=l"(d) : "f"(v));
    return d;
}
__device__ __forceinline__ float2 unpk(ull a) {
    float2 r;
    asm("mov.b64 {%0, %1}, %2;" : "=f"(r.x), "=f"(r.y) : "l"(a));
    return r;
}

// ---------------------------------------------------------------------------
// conv1 + relu + maxpool2.  (R2 inner loop; vectorized float4 fill)
// Block: pooled tile 16(rows) x 32(cols). 256 threads = 16x16; each thread
// computes 2 adjacent pooled outputs (2x4 conv patch) for all 6 oc.
// ---------------------------------------------------------------------------
__global__ __launch_bounds__(256) void conv1_kernel(
    const float* __restrict__ img, const float* __restrict__ w,
    const float* __restrict__ bias) {
    __shared__ float sin[3][36 * 69];
    __shared__ float2 swp[3 * 25 * 3];   // [(ic*25+k)*3 + p]
    __shared__ float sb[6];
    const int bz = blockIdx.z, by = blockIdx.y, bx = blockIdx.x;
    const int tid = threadIdx.x;

    if (tid < 225) {
        int p = tid % 3, ick = tid / 3;
        int ic = ick / 25, k = ick % 25;
        swp[tid] = make_float2(w[(2 * p) * 75 + ic * 25 + k],
                               w[(2 * p + 1) * 75 + ic * 25 + k]);
    }
    if (tid < 6) sb[tid] = bias[tid];

    const int iy0 = by * 32, ix0 = bx * 64;
    // vectorized fill: 68 cols = 17 float4 per row; 3*36*17 = 1836 quads
    for (int e = tid; e < 1836; e += 256) {
        int ic = e / 612, rem = e % 612, r = rem / 17, c4 = rem % 17;
        int gy = iy0 + r, gx = ix0 + 4 * c4;
        float4 v;
        if (gy < 416 && gx <= 412) {
            v = *(const float4*)&img[((size_t)bz * 3 + ic) * 416 * 416 +
                                     gy * 416 + gx];
        } else {
            const float* src = img + ((size_t)bz * 3 + ic) * 416 * 416;
            v.x = (gy < 416 && gx < 416) ? src[gy * 416 + gx] : 0.f;
            v.y = (gy < 416 && gx + 1 < 416) ? src[gy * 416 + gx + 1] : 0.f;
            v.z = (gy < 416 && gx + 2 < 416) ? src[gy * 416 + gx + 2] : 0.f;
            v.w = (gy < 416 && gx + 3 < 416) ? src[gy * 416 + gx + 3] : 0.f;
        }
        float* dst = &sin[ic][r * 69 + 4 * c4];
        dst[0] = v.x; dst[1] = v.y; dst[2] = v.z; dst[3] = v.w;
    }
    __syncthreads();

    const int ty = tid >> 4, tx = tid & 15;
    ull acc[3][2][4];
#pragma unroll
    for (int p = 0; p < 3; p++)
#pragma unroll
        for (int r = 0; r < 2; r++)
#pragma unroll
            for (int c = 0; c < 4; c++) acc[p][r][c] = 0ull;

    for (int ic = 0; ic < 3; ic++) {
        const float* S = &sin[ic][(2 * ty) * 69 + 4 * tx];
        const ull* W = (const ull*)&swp[ic * 75];
        ull RA[8], RB[8];
#pragma unroll
        for (int c = 0; c < 8; c++) RA[c] = dup2(S[c]);
#pragma unroll
        for (int ky = 0; ky < 5; ky++) {
            const float* Srow = S + (ky + 1) * 69;
#pragma unroll
            for (int c = 0; c < 8; c++) RB[c] = dup2(Srow[c]);
#pragma unroll
            for (int kx = 0; kx < 5; kx++) {
#pragma unroll
                for (int p = 0; p < 3; p++) {
                    ull wv = W[(ky * 5 + kx) * 3 + p];
#pragma unroll
                    for (int c = 0; c < 4; c++) {
                        acc[p][0][c] = fma2(RA[kx + c], wv, acc[p][0][c]);
                        acc[p][1][c] = fma2(RB[kx + c], wv, acc[p][1][c]);
                    }
                }
            }
#pragma unroll
            for (int c = 0; c < 8; c++) RA[c] = RB[c];
        }
    }

    const int py = by * 16 + ty;
    if (py < 206) {
#pragma unroll
        for (int d = 0; d < 2; d++) {
            const int px = bx * 32 + 2 * tx + d;
            if (px < 206) {
#pragma unroll
                for (int p = 0; p < 3; p++) {
                    float2 a00 = unpk(acc[p][0][2 * d]);
                    float2 a01 = unpk(acc[p][0][2 * d + 1]);
                    float2 a10 = unpk(acc[p][1][2 * d]);
                    float2 a11 = unpk(acc[p][1][2 * d + 1]);
                    float vlo = fmaxf(fmaxf(a00.x, a01.x), fmaxf(a10.x, a11.x));
                    float vhi = fmaxf(fmaxf(a00.y, a01.y), fmaxf(a10.y, a11.y));
                    g_pool1[(((size_t)bz * 6 + 2 * p) * 208 + py) * 208 + px] =
                        fmaxf(vlo + sb[2 * p], 0.f);
                    g_pool1[(((size_t)bz * 6 + 2 * p + 1) * 208 + py) * 208 + px] =
                        fmaxf(vhi + sb[2 * p + 1], 0.f);
                }
            }
        }
    }
}

// ---------------------------------------------------------------------------
// conv2 + relu + maxpool2.  (R2 inner loop; vectorized fill from padded pool1)
// Block: pooled tile 16x16, 16 oc. 256 threads = 2 oc-groups x (16x8);
// each thread: 2 pooled outputs (2x4 conv patch) for 8 oc (4 oc-pairs).
// ---------------------------------------------------------------------------
__global__ __launch_bounds__(256) void conv2_kernel(
    const float* __restrict__ w, const float* __restrict__ bias) {
    __shared__ float sin[6][36 * 37];
    __shared__ float2 swp[6 * 25 * 8];   // [(ic*25+k)*8 + p]
    __shared__ float sb[16];
    const int bz = blockIdx.z, by = blockIdx.y, bx = blockIdx.x;
    const int tid = threadIdx.x;

    for (int i = tid; i < 1200; i += 256) {
        int p = i % 8, ick = i / 8;
        int ic = ick / 25, k = ick % 25;
        swp[i] = make_float2(w[((2 * p) * 6 + ic) * 25 + k],
                             w[((2 * p + 1) * 6 + ic) * 25 + k]);
    }
    if (tid < 16) sb[tid] = bias[tid];

    const int iy0 = by * 32, ix0 = bx * 32;
    // vectorized fill: 36 cols = 9 float4 per row; 6*36*9 = 1944 quads.
    // pool1 padded to 208x208 with zero padding -> in-bounds vec loads whose
    // tail lanes fall in cols 206..207 read zeros, matching the mask.
    for (int e = tid; e < 1944; e += 256) {
        int ic = e / 324, rem = e % 324, r = rem / 9, c4 = rem % 9;
        int gy = iy0 + r, gx = ix0 + 4 * c4;
        const float* src = g_pool1 + ((size_t)bz * 6 + ic) * 208 * 208;
        float4 v;
        if (gy < 206 && gx <= 204) {
            v = *(const float4*)&src[gy * 208 + gx];
        } else {
            v.x = (gy < 206 && gx < 206) ? src[gy * 208 + gx] : 0.f;
            v.y = (gy < 206 && gx + 1 < 206) ? src[gy * 208 + gx + 1] : 0.f;
            v.z = (gy < 206 && gx + 2 < 206) ? src[gy * 208 + gx + 2] : 0.f;
            v.w = (gy < 206 && gx + 3 < 206) ? src[gy * 208 + gx + 3] : 0.f;
        }
        float* dst = &sin[ic][r * 37 + 4 * c4];
        dst[0] = v.x; dst[1] = v.y; dst[2] = v.z; dst[3] = v.w;
    }
    __syncthreads();

    const int og = tid >> 7;            // 0..1 -> oc base 8*og
    const int t = tid & 127;
    const int ty = t >> 3, tx = t & 7;
    ull acc[4][2][4];
#pragma unroll
    for (int p = 0; p < 4; p++)
#pragma unroll
        for (int r = 0; r < 2; r++)
#pragma unroll
            for (int c = 0; c < 4; c++) acc[p][r][c] = 0ull;

    for (int ic = 0; ic < 6; ic++) {
        const float* S = &sin[ic][(2 * ty) * 37 + 4 * tx];
        const ull* W = (const ull*)&swp[ic * 200 + 4 * og];
        ull RA[8], RB[8];
#pragma unroll
        for (int c = 0; c < 8; c++) RA[c] = dup2(S[c]);
#pragma unroll
        for (int ky = 0; ky < 5; ky++) {
            const float* Srow = S + (ky + 1) * 37;
#pragma unroll
            for (int c = 0; c < 8; c++) RB[c] = dup2(Srow[c]);
#pragma unroll
            for (int kx = 0; kx < 5; kx++) {
#pragma unroll
                for (int p = 0; p < 4; p++) {
                    ull wv = W[(ky * 5 + kx) * 8 + p];
#pragma unroll
                    for (int c = 0; c < 4; c++) {
                        acc[p][0][c] = fma2(RA[kx + c], wv, acc[p][0][c]);
                        acc[p][1][c] = fma2(RB[kx + c], wv, acc[p][1][c]);
                    }
                }
            }
#pragma unroll
            for (int c = 0; c < 8; c++) RA[c] = RB[c];
        }
    }

    const int py = by * 16 + ty;
    if (py < 101) {
#pragma unroll
        for (int d = 0; d < 2; d++) {
            const int px = bx * 16 + 2 * tx + d;
            if (px < 101) {
#pragma unroll
                for (int p = 0; p < 4; p++) {
                    const int oc = 8 * og + 2 * p;
                    float2 a00 = unpk(acc[p][0][2 * d]);
                    float2 a01 = unpk(acc[p][0][2 * d + 1]);
                    float2 a10 = unpk(acc[p][1][2 * d]);
                    float2 a11 = unpk(acc[p][1][2 * d + 1]);
                    float vlo = fmaxf(fmaxf(a00.x, a01.x), fmaxf(a10.x, a11.x));
                    float vhi = fmaxf(fmaxf(a00.y, a01.y), fmaxf(a10.y, a11.y));
                    g_pool2[(((size_t)bz * 16 + oc) * 101 + py) * 101 + px] =
                        fmaxf(vlo + sb[oc], 0.f);
                    g_pool2[(((size_t)bz * 16 + oc + 1) * 101 + py) * 101 + px] =
                        fmaxf(vhi + sb[oc + 1], 0.f);
                }
            }
        }
    }
}

// ---------------------------------------------------------------------------
// fc1 split-K (scalar R2 version — measured best). 101 blocks, 64x64 partial
// each over a 1616-long K-chunk. 256 threads as 16x16, 4x4 register tile.
// ---------------------------------------------------------------------------
__global__ __launch_bounds__(256) void fc1_kernel(const float* __restrict__ w) {
    __shared__ float xs[64][17];
    __shared__ float ws[64][17];
    const int blk = blockIdx.x;
    const int tid = threadIdx.x;
    const int tb = tid >> 4, to = tid & 15;
    float acc[4][4];
#pragma unroll
    for (int i = 0; i < 4; i++)
#pragma unroll
        for (int j = 0; j < 4; j++) acc[i][j] = 0.f;

    const int k0 = blk * 1616;
    for (int s = 0; s < 101; s++) {
        const int kbase = k0 + s * 16;
#pragma unroll
        for (int i = 0; i < 4; i++) {
            int e = tid + i * 256;
            int row = e >> 4, col = e & 15;
            xs[row][col] = g_pool2[(size_t)row * 163216 + kbase + col];
            ws[row][col] = w[(size_t)row * 163216 + kbase + col];
        }
        __syncthreads();
#pragma unroll
        for (int kk = 0; kk < 16; kk++) {
            float xr[4], wr[4];
#pragma unroll
            for (int i = 0; i < 4; i++) xr[i] = xs[tb + 16 * i][kk];
#pragma unroll
            for (int j = 0; j < 4; j++) wr[j] = ws[to + 16 * j][kk];
#pragma unroll
            for (int i = 0; i < 4; i++)
#pragma unroll
                for (int j = 0; j < 4; j++)
                    acc[i][j] = fmaf(xr[i], wr[j], acc[i][j]);
        }
        __syncthreads();
    }

    float* outp = g_fc1part + (size_t)blk * 4096;
#pragma unroll
    for (int i = 0; i < 4; i++)
#pragma unroll
        for (int j = 0; j < 4; j++)
            outp[(tb + 16 * i) * 64 + (to + 16 * j)] = acc[i][j];
}

// ---------------------------------------------------------------------------
// fc1 finalize + box decode. 64 blocks, coalesced reduction over partials.
// ---------------------------------------------------------------------------
__global__ __launch_bounds__(256) void fc1_finalize_boxes(
    const float* __restrict__ fc1_b) {
    __shared__ float partial[4][64];
    __shared__ float xv[64];
    const int b = blockIdx.x;
    const int tid = threadIdx.x;
    const int j = tid & 63, ch = tid >> 6;
    float s = 0.f;
    for (int t = ch; t < 101; t += 4)
        s += g_fc1part[t * 4096 + b * 64 + j];
    partial[ch][j] = s;
    __syncthreads();
    if (tid < 64) {
        float v = partial[0][tid] + partial[1][tid] + partial[2][tid] +
                  partial[3][tid] + fc1_b[tid];
        xv[tid] = fmaxf(v, 0.f);
    }
    __syncthreads();
    if (tid < 16) {
        const int i = tid;
        float x1 = fminf(fmaxf(rintf(xv[i] * 0.5f), 0.f), 415.f);
        float y1 = fminf(fmaxf(rintf(xv[16 + i] * 0.5f), 0.f), 415.f);
        float x2 = fminf(fmaxf(rintf(xv[32 + i] * 0.5f), 0.f), 415.f);
        float y2 = fminf(fmaxf(rintf(xv[48 + i] * 0.5f), 0.f), 415.f);
        float bw = fmaxf(x2 - x1 + 1.f, 1.f) * (1.f / 16.f);
        float bh = fmaxf(y2 - y1 + 1.f, 1.f) * (1.f / 16.f);
        g_roi[b * 16 + i] = make_float4(x1, y1, bw, bh);
    }
}

// ---------------------------------------------------------------------------
// Fused RoIPool + 4x4 conv + fc2. One block per roi.  (R2 naive version —
// measured best; L2 reuse across the 16 rois/image absorbs the scatter)
// ---------------------------------------------------------------------------
__global__ __launch_bounds__(256) void roi_kernel(
    const float* __restrict__ img, const float* __restrict__ rw,
    const float* __restrict__ rb, const float* __restrict__ w2,
    const float* __restrict__ b2, float* __restrict__ out) {
    __shared__ float pooled[3][16][16];
    __shared__ float yv[169];
    __shared__ float swc[48];
    __shared__ float sbc;
    const int n = blockIdx.x, tid = threadIdx.x;

    if (tid < 48) swc[tid] = rw[tid];
    if (tid == 0) sbc = rb[0];

    const float4 p = g_roi[n];   // x1, y1, bw, bh
    const int b = n >> 4;
    const int ph = tid >> 4, pw = tid & 15;

    const int hs = (int)fminf(floorf((float)ph * p.w) + p.y, 416.f);
    const int he = (int)fminf(ceilf((float)(ph + 1) * p.w) + p.y, 416.f);
    const int wsb = (int)fminf(floorf((float)pw * p.z) + p.x, 416.f);
    const int web = (int)fminf(ceilf((float)(pw + 1) * p.z) + p.x, 416.f);

    float m0, m1, m2;
    if (he > hs && web > wsb) {
        m0 = m1 = m2 = -3.4e38f;
        const float* c0 = img + (size_t)b * 3 * 416 * 416;
        for (int yy = hs; yy < he; yy++) {
            const float* row = c0 + yy * 416;
            for (int xx = wsb; xx < web; xx++) {
                m0 = fmaxf(m0, row[xx]);
                m1 = fmaxf(m1, row[xx + 416 * 416]);
                m2 = fmaxf(m2, row[xx + 2 * 416 * 416]);
            }
        }
    } else {
        m0 = m1 = m2 = 0.f;
    }
    pooled[0][ph][pw] = m0;
    pooled[1][ph][pw] = m1;
    pooled[2][ph][pw] = m2;
    __syncthreads();

    if (tid < 169) {
        const int oy = tid / 13, ox = tid % 13;
        float s = sbc;
#pragma unroll
        for (int c = 0; c < 3; c++)
#pragma unroll
            for (int ky = 0; ky < 4; ky++)
#pragma unroll
                for (int kx = 0; kx < 4; kx++)
                    s = fmaf(pooled[c][oy + ky][ox + kx],
                             swc[(c * 4 + ky) * 4 + kx], s);
        yv[tid] = fmaxf(s, 0.f);
    }
    __syncthreads();

    if (tid < 64) {
        float s = b2[tid];
        const float* wr = w2 + tid * 169;
        for (int pp = 0; pp < 169; pp++) s = fmaf(yv[pp], __ldg(&wr[pp]), s);
        out[(size_t)n * 64 + tid] = fmaxf(s, 0.f);
    }
}

// ---------------------------------------------------------------------------
extern "C" void kernel_launch(void* const* d_in, const int* in_sizes, int n_in,
                              void* d_out, int out_size) {
    const float* img     = (const float*)d_in[0];
    const float* conv1_w = (const float*)d_in[1];
    const float* conv1_b = (const float*)d_in[2];
    const float* conv2_w = (const float*)d_in[3];
    const float* conv2_b = (const float*)d_in[4];
    const float* fc1_w   = (const float*)d_in[5];
    const float* fc1_b   = (const float*)d_in[6];
    const float* roi_w   = (const float*)d_in[7];
    const float* roi_b   = (const float*)d_in[8];
    const float* fc2_w   = (const float*)d_in[9];
    const float* fc2_b   = (const float*)d_in[10];
    float* out = (float*)d_out;

    dim3 g1(7, 13, 64);    // pooled 206: x 7*32=224, y 13*16=208
    conv1_kernel<<<g1, 256>>>(img, conv1_w, conv1_b);

    dim3 g2(7, 7, 64);     // pooled 101: 7*16=112 both dims
    conv2_kernel<<<g2, 256>>>(conv2_w, conv2_b);

    fc1_kernel<<<101, 256>>>(fc1_w);
    fc1_finalize_boxes<<<64, 256>>>(fc1_b);
    roi_kernel<<<1024, 256>>>(img, roi_w, roi_b, fc2_w, fc2_b, out);
}

// round 8
// speedup vs baseline: 1.1958x; 1.0771x over previous
#include <cuda_runtime.h>
#include <cstdint>

typedef unsigned long long ull;

// ---------------------------------------------------------------------------
//   img      [64][3][416][416]
//   conv1    5x5 VALID -> relu -> pool2 -> [64][6][206][206] (stored 208x208 padded)
//   conv2    5x5 VALID -> relu -> pool2 -> [64][16][101][101]
//   fc1      [64][163216] -> relu -> [64][64] -> boxes [1024][4]
//   roipool  -> [1024][3][16][16] -> 4x4 conv -> relu -> fc2 -> [1024][64]
// ---------------------------------------------------------------------------

// padded 208x208; rows/cols 206..207 never written -> static zero-init
// provides the zero padding conv2's loads expect.
__device__ float g_pool1[64 * 6 * 208 * 208];
__device__ float g_pool2[64 * 16 * 101 * 101];
__device__ float g_fc1part[101 * 64 * 64];
__device__ float4 g_roi[1024];

// ---- packed fp32x2 helpers ------------------------------------------------
__device__ __forceinline__ ull fma2(ull a, ull b, ull c) {
    ull d;
    asm("fma.rn.f32x2 %0, %1, %2, %3;" : "=l"(d) : "l"(a), "l"(b), "l"(c));
    return d;
}
__device__ __forceinline__ ull dup2(float v) {
    ull d;
    asm("mov.b64 %0, {%1, %1};" : "=l"(d) : "f"(v));
    return d;
}
__device__ __forceinline__ float2 unpk(ull a) {
    float2 r;
    asm("mov.b64 {%0, %1}, %2;" : "=f"(r.x), "=f"(r.y) : "l"(a));
    return r;
}

// ---------------------------------------------------------------------------
// conv1 + relu + maxpool2.  (R7 version — measured best)
// ---------------------------------------------------------------------------
__global__ __launch_bounds__(256) void conv1_kernel(
    const float* __restrict__ img, const float* __restrict__ w,
    const float* __restrict__ bias) {
    __shared__ float sin[3][36 * 69];
    __shared__ float2 swp[3 * 25 * 3];   // [(ic*25+k)*3 + p]
    __shared__ float sb[6];
    const int bz = blockIdx.z, by = blockIdx.y, bx = blockIdx.x;
    const int tid = threadIdx.x;

    if (tid < 225) {
        int p = tid % 3, ick = tid / 3;
        int ic = ick / 25, k = ick % 25;
        swp[tid] = make_float2(w[(2 * p) * 75 + ic * 25 + k],
                               w[(2 * p + 1) * 75 + ic * 25 + k]);
    }
    if (tid < 6) sb[tid] = bias[tid];

    const int iy0 = by * 32, ix0 = bx * 64;
    for (int e = tid; e < 1836; e += 256) {
        int ic = e / 612, rem = e % 612, r = rem / 17, c4 = rem % 17;
        int gy = iy0 + r, gx = ix0 + 4 * c4;
        float4 v;
        if (gy < 416 && gx <= 412) {
            v = *(const float4*)&img[((size_t)bz * 3 + ic) * 416 * 416 +
                                     gy * 416 + gx];
        } else {
            const float* src = img + ((size_t)bz * 3 + ic) * 416 * 416;
            v.x = (gy < 416 && gx < 416) ? src[gy * 416 + gx] : 0.f;
            v.y = (gy < 416 && gx + 1 < 416) ? src[gy * 416 + gx + 1] : 0.f;
            v.z = (gy < 416 && gx + 2 < 416) ? src[gy * 416 + gx + 2] : 0.f;
            v.w = (gy < 416 && gx + 3 < 416) ? src[gy * 416 + gx + 3] : 0.f;
        }
        float* dst = &sin[ic][r * 69 + 4 * c4];
        dst[0] = v.x; dst[1] = v.y; dst[2] = v.z; dst[3] = v.w;
    }
    __syncthreads();

    const int ty = tid >> 4, tx = tid & 15;
    ull acc[3][2][4];
#pragma unroll
    for (int p = 0; p < 3; p++)
#pragma unroll
        for (int r = 0; r < 2; r++)
#pragma unroll
            for (int c = 0; c < 4; c++) acc[p][r][c] = 0ull;

    for (int ic = 0; ic < 3; ic++) {
        const float* S = &sin[ic][(2 * ty) * 69 + 4 * tx];
        const ull* W = (const ull*)&swp[ic * 75];
        ull RA[8], RB[8];
#pragma unroll
        for (int c = 0; c < 8; c++) RA[c] = dup2(S[c]);
#pragma unroll
        for (int ky = 0; ky < 5; ky++) {
            const float* Srow = S + (ky + 1) * 69;
#pragma unroll
            for (int c = 0; c < 8; c++) RB[c] = dup2(Srow[c]);
#pragma unroll
            for (int kx = 0; kx < 5; kx++) {
#pragma unroll
                for (int p = 0; p < 3; p++) {
                    ull wv = W[(ky * 5 + kx) * 3 + p];
#pragma unroll
                    for (int c = 0; c < 4; c++) {
                        acc[p][0][c] = fma2(RA[kx + c], wv, acc[p][0][c]);
                        acc[p][1][c] = fma2(RB[kx + c], wv, acc[p][1][c]);
                    }
                }
            }
#pragma unroll
            for (int c = 0; c < 8; c++) RA[c] = RB[c];
        }
    }

    const int py = by * 16 + ty;
    if (py < 206) {
#pragma unroll
        for (int d = 0; d < 2; d++) {
            const int px = bx * 32 + 2 * tx + d;
            if (px < 206) {
#pragma unroll
                for (int p = 0; p < 3; p++) {
                    float2 a00 = unpk(acc[p][0][2 * d]);
                    float2 a01 = unpk(acc[p][0][2 * d + 1]);
                    float2 a10 = unpk(acc[p][1][2 * d]);
                    float2 a11 = unpk(acc[p][1][2 * d + 1]);
                    float vlo = fmaxf(fmaxf(a00.x, a01.x), fmaxf(a10.x, a11.x));
                    float vhi = fmaxf(fmaxf(a00.y, a01.y), fmaxf(a10.y, a11.y));
                    g_pool1[(((size_t)bz * 6 + 2 * p) * 208 + py) * 208 + px] =
                        fmaxf(vlo + sb[2 * p], 0.f);
                    g_pool1[(((size_t)bz * 6 + 2 * p + 1) * 208 + py) * 208 + px] =
                        fmaxf(vhi + sb[2 * p + 1], 0.f);
                }
            }
        }
    }
}

// ---------------------------------------------------------------------------
// conv2 + relu + maxpool2.  NEW: tile 16x8 pooled, 4 oc-groups of 4 oc
// (2 f32x2 pairs/thread), 2x4 conv patch per thread (2 pooled outputs).
// Grid (13,7,64): waste 14.2% (was 23.3%); ~80 regs -> 3 blocks/SM;
// per-ky LDS 18 for 80 fma2 (was 23 for 80).
// ---------------------------------------------------------------------------
__global__ __launch_bounds__(256) void conv2_kernel(
    const float* __restrict__ w, const float* __restrict__ bias) {
    __shared__ float sin[6][36 * 21];
    __shared__ float2 swp[6 * 25 * 8];   // [(ic*25+k)*8 + p]
    __shared__ float sb[16];
    const int bz = blockIdx.z, by = blockIdx.y, bx = blockIdx.x;
    const int tid = threadIdx.x;

    for (int i = tid; i < 1200; i += 256) {
        int p = i % 8, ick = i / 8;
        int ic = ick / 25, k = ick % 25;
        swp[i] = make_float2(w[((2 * p) * 6 + ic) * 25 + k],
                             w[((2 * p + 1) * 6 + ic) * 25 + k]);
    }
    if (tid < 16) sb[tid] = bias[tid];

    const int iy0 = by * 32, ix0 = bx * 16;
    // fill: 20 input cols = 5 quads/row; 6*36*5 = 1080 quads from padded pool1
    for (int e = tid; e < 1080; e += 256) {
        int ic = e / 180, rem = e % 180, r = rem / 5, c4 = rem % 5;
        int gy = iy0 + r, gx = ix0 + 4 * c4;
        const float* src = g_pool1 + ((size_t)bz * 6 + ic) * 208 * 208;
        float4 v;
        if (gy < 208 && gx <= 204) {
            v = *(const float4*)&src[gy * 208 + gx];
        } else {
            v.x = (gy < 208 && gx < 208) ? src[gy * 208 + gx] : 0.f;
            v.y = (gy < 208 && gx + 1 < 208) ? src[gy * 208 + gx + 1] : 0.f;
            v.z = (gy < 208 && gx + 2 < 208) ? src[gy * 208 + gx + 2] : 0.f;
            v.w = (gy < 208 && gx + 3 < 208) ? src[gy * 208 + gx + 3] : 0.f;
        }
        float* dst = &sin[ic][r * 21 + 4 * c4];
        dst[0] = v.x; dst[1] = v.y; dst[2] = v.z; dst[3] = v.w;
    }
    __syncthreads();

    const int o = tid >> 6;             // 0..3 -> oc base 4*o (pairs 2o, 2o+1)
    const int t = tid & 63;
    const int ty = t >> 2, tx = t & 3;  // ty 0..15, tx 0..3
    ull acc[2][2][4];
#pragma unroll
    for (int p = 0; p < 2; p++)
#pragma unroll
        for (int r = 0; r < 2; r++)
#pragma unroll
            for (int c = 0; c < 4; c++) acc[p][r][c] = 0ull;

    for (int ic = 0; ic < 6; ic++) {
        const float* S = &sin[ic][(2 * ty) * 21 + 4 * tx];
        const ull* W = (const ull*)&swp[ic * 200 + 2 * o];
        ull RA[8], RB[8];
#pragma unroll
        for (int c = 0; c < 8; c++) RA[c] = dup2(S[c]);
#pragma unroll
        for (int ky = 0; ky < 5; ky++) {
            const float* Srow = S + (ky + 1) * 21;
#pragma unroll
            for (int c = 0; c < 8; c++) RB[c] = dup2(Srow[c]);
#pragma unroll
            for (int kx = 0; kx < 5; kx++) {
#pragma unroll
                for (int p = 0; p < 2; p++) {
                    ull wv = W[(ky * 5 + kx) * 8 + p];
#pragma unroll
                    for (int c = 0; c < 4; c++) {
                        acc[p][0][c] = fma2(RA[kx + c], wv, acc[p][0][c]);
                        acc[p][1][c] = fma2(RB[kx + c], wv, acc[p][1][c]);
                    }
                }
            }
#pragma unroll
            for (int c = 0; c < 8; c++) RA[c] = RB[c];
        }
    }

    const int py = by * 16 + ty;
    if (py < 101) {
#pragma unroll
        for (int d = 0; d < 2; d++) {
            const int px = bx * 8 + 2 * tx + d;
            if (px < 101) {
#pragma unroll
                for (int p = 0; p < 2; p++) {
                    const int oc = 4 * o + 2 * p;
                    float2 a00 = unpk(acc[p][0][2 * d]);
                    float2 a01 = unpk(acc[p][0][2 * d + 1]);
                    float2 a10 = unpk(acc[p][1][2 * d]);
                    float2 a11 = unpk(acc[p][1][2 * d + 1]);
                    float vlo = fmaxf(fmaxf(a00.x, a01.x), fmaxf(a10.x, a11.x));
                    float vhi = fmaxf(fmaxf(a00.y, a01.y), fmaxf(a10.y, a11.y));
                    g_pool2[(((size_t)bz * 16 + oc) * 101 + py) * 101 + px] =
                        fmaxf(vlo + sb[oc], 0.f);
                    g_pool2[(((size_t)bz * 16 + oc + 1) * 101 + py) * 101 + px] =
                        fmaxf(vhi + sb[oc + 1], 0.f);
                }
            }
        }
    }
}

// ---------------------------------------------------------------------------
// fc1 split-K (scalar R2 version — measured best).
// ---------------------------------------------------------------------------
__global__ __launch_bounds__(256) void fc1_kernel(const float* __restrict__ w) {
    __shared__ float xs[64][17];
    __shared__ float ws[64][17];
    const int blk = blockIdx.x;
    const int tid = threadIdx.x;
    const int tb = tid >> 4, to = tid & 15;
    float acc[4][4];
#pragma unroll
    for (int i = 0; i < 4; i++)
#pragma unroll
        for (int j = 0; j < 4; j++) acc[i][j] = 0.f;

    const int k0 = blk * 1616;
    for (int s = 0; s < 101; s++) {
        const int kbase = k0 + s * 16;
#pragma unroll
        for (int i = 0; i < 4; i++) {
            int e = tid + i * 256;
            int row = e >> 4, col = e & 15;
            xs[row][col] = g_pool2[(size_t)row * 163216 + kbase + col];
            ws[row][col] = w[(size_t)row * 163216 + kbase + col];
        }
        __syncthreads();
#pragma unroll
        for (int kk = 0; kk < 16; kk++) {
            float xr[4], wr[4];
#pragma unroll
            for (int i = 0; i < 4; i++) xr[i] = xs[tb + 16 * i][kk];
#pragma unroll
            for (int j = 0; j < 4; j++) wr[j] = ws[to + 16 * j][kk];
#pragma unroll
            for (int i = 0; i < 4; i++)
#pragma unroll
                for (int j = 0; j < 4; j++)
                    acc[i][j] = fmaf(xr[i], wr[j], acc[i][j]);
        }
        __syncthreads();
    }

    float* outp = g_fc1part + (size_t)blk * 4096;
#pragma unroll
    for (int i = 0; i < 4; i++)
#pragma unroll
        for (int j = 0; j < 4; j++)
            outp[(tb + 16 * i) * 64 + (to + 16 * j)] = acc[i][j];
}

// ---------------------------------------------------------------------------
// fc1 finalize + box decode. 64 blocks, coalesced reduction over partials.
// ---------------------------------------------------------------------------
__global__ __launch_bounds__(256) void fc1_finalize_boxes(
    const float* __restrict__ fc1_b) {
    __shared__ float partial[4][64];
    __shared__ float xv[64];
    const int b = blockIdx.x;
    const int tid = threadIdx.x;
    const int j = tid & 63, ch = tid >> 6;
    float s = 0.f;
    for (int t = ch; t < 101; t += 4)
        s += g_fc1part[t * 4096 + b * 64 + j];
    partial[ch][j] = s;
    __syncthreads();
    if (tid < 64) {
        float v = partial[0][tid] + partial[1][tid] + partial[2][tid] +
                  partial[3][tid] + fc1_b[tid];
        xv[tid] = fmaxf(v, 0.f);
    }
    __syncthreads();
    if (tid < 16) {
        const int i = tid;
        float x1 = fminf(fmaxf(rintf(xv[i] * 0.5f), 0.f), 415.f);
        float y1 = fminf(fmaxf(rintf(xv[16 + i] * 0.5f), 0.f), 415.f);
        float x2 = fminf(fmaxf(rintf(xv[32 + i] * 0.5f), 0.f), 415.f);
        float y2 = fminf(fmaxf(rintf(xv[48 + i] * 0.5f), 0.f), 415.f);
        float bw = fmaxf(x2 - x1 + 1.f, 1.f) * (1.f / 16.f);
        float bh = fmaxf(y2 - y1 + 1.f, 1.f) * (1.f / 16.f);
        g_roi[b * 16 + i] = make_float4(x1, y1, bw, bh);
    }
}

// ---------------------------------------------------------------------------
// Fused RoIPool + 4x4 conv + fc2. One block per roi.  (naive — measured best)
// ---------------------------------------------------------------------------
__global__ __launch_bounds__(256) void roi_kernel(
    const float* __restrict__ img, const float* __restrict__ rw,
    const float* __restrict__ rb, const float* __restrict__ w2,
    const float* __restrict__ b2, float* __restrict__ out) {
    __shared__ float pooled[3][16][16];
    __shared__ float yv[169];
    __shared__ float swc[48];
    __shared__ float sbc;
    const int n = blockIdx.x, tid = threadIdx.x;

    if (tid < 48) swc[tid] = rw[tid];
    if (tid == 0) sbc = rb[0];

    const float4 p = g_roi[n];   // x1, y1, bw, bh
    const int b = n >> 4;
    const int ph = tid >> 4, pw = tid & 15;

    const int hs = (int)fminf(floorf((float)ph * p.w) + p.y, 416.f);
    const int he = (int)fminf(ceilf((float)(ph + 1) * p.w) + p.y, 416.f);
    const int wsb = (int)fminf(floorf((float)pw * p.z) + p.x, 416.f);
    const int web = (int)fminf(ceilf((float)(pw + 1) * p.z) + p.x, 416.f);

    float m0, m1, m2;
    if (he > hs && web > wsb) {
        m0 = m1 = m2 = -3.4e38f;
        const float* c0 = img + (size_t)b * 3 * 416 * 416;
        for (int yy = hs; yy < he; yy++) {
            const float* row = c0 + yy * 416;
            for (int xx = wsb; xx < web; xx++) {
                m0 = fmaxf(m0, row[xx]);
                m1 = fmaxf(m1, row[xx + 416 * 416]);
                m2 = fmaxf(m2, row[xx + 2 * 416 * 416]);
            }
        }
    } else {
        m0 = m1 = m2 = 0.f;
    }
    pooled[0][ph][pw] = m0;
    pooled[1][ph][pw] = m1;
    pooled[2][ph][pw] = m2;
    __syncthreads();

    if (tid < 169) {
        const int oy = tid / 13, ox = tid % 13;
        float s = sbc;
#pragma unroll
        for (int c = 0; c < 3; c++)
#pragma unroll
            for (int ky = 0; ky < 4; ky++)
#pragma unroll
                for (int kx = 0; kx < 4; kx++)
                    s = fmaf(pooled[c][oy + ky][ox + kx],
                             swc[(c * 4 + ky) * 4 + kx], s);
        yv[tid] = fmaxf(s, 0.f);
    }
    __syncthreads();

    if (tid < 64) {
        float s = b2[tid];
        const float* wr = w2 + tid * 169;
        for (int pp = 0; pp < 169; pp++) s = fmaf(yv[pp], __ldg(&wr[pp]), s);
        out[(size_t)n * 64 + tid] = fmaxf(s, 0.f);
    }
}

// ---------------------------------------------------------------------------
extern "C" void kernel_launch(void* const* d_in, const int* in_sizes, int n_in,
                              void* d_out, int out_size) {
    const float* img     = (const float*)d_in[0];
    const float* conv1_w = (const float*)d_in[1];
    const float* conv1_b = (const float*)d_in[2];
    const float* conv2_w = (const float*)d_in[3];
    const float* conv2_b = (const float*)d_in[4];
    const float* fc1_w   = (const float*)d_in[5];
    const float* fc1_b   = (const float*)d_in[6];
    const float* roi_w   = (const float*)d_in[7];
    const float* roi_b   = (const float*)d_in[8];
    const float* fc2_w   = (const float*)d_in[9];
    const float* fc2_b   = (const float*)d_in[10];
    float* out = (float*)d_out;

    dim3 g1(7, 13, 64);    // pooled 206: x 7*32=224, y 13*16=208
    conv1_kernel<<<g1, 256>>>(img, conv1_w, conv1_b);

    dim3 g2(13, 7, 64);    // pooled 101: x 13*8=104, y 7*16=112
    conv2_kernel<<<g2, 256>>>(conv2_w, conv2_b);

    fc1_kernel<<<101, 256>>>(fc1_w);
    fc1_finalize_boxes<<<64, 256>>>(fc1_b);
    roi_kernel<<<1024, 256>>>(img, roi_w, roi_b, fc2_w, fc2_b, out);
}